// round 11
// baseline (speedup 1.0000x reference)
#include <cuda_runtime.h>
#include <cstdint>

// x: (16, 512, 32, 32) f32 | p_mu, p_logvar: (16384, 512) f32 | out: scalar f32
#define DD      512
#define HWSZ    1024
#define NN      16384
#define NUNITS  2048            // units of 8 tokens
#define NBLOCKS 148             // persistent, one per SM
#define SROW    516             // padded x-tile row stride (floats): aligned LDS.128, conflict-free STS

__device__ double g_sx[DD];
__device__ double g_sx2[DD];
__device__ double g_siv[DD];
__device__ double g_smuiv[DD];
__device__ double g_P;
__device__ double g_R;
__device__ int    g_done;       // arrival counter; reset by finalizer

__global__ __launch_bounds__(1024)
void club_persist(const float* __restrict__ x,
                  const float* __restrict__ mu,
                  const float* __restrict__ lv,
                  float* __restrict__ out)
{
    const int tid  = threadIdx.x;
    const int lane = tid & 31;
    const int warp = tid >> 5;          // 0..31
    const int c    = blockIdx.x;

    // compute role: token row t (uniform per warp), d = 4*dg..4*dg+3 (fixed)
    const int t  = tid >> 7;            // 0..7
    const int dg = tid & 127;           // 0..127

    // x loader role: row d = tid>>1, hw half h = tid&1 (full 32B sectors, nL=16/warp)
    const int ld = tid >> 1;
    const int lh = (tid & 1) * 4;

    __shared__ float  xs[2][8 * SROW];  // x tiles [local hw 0..7][d]
    __shared__ double sred[32];
    __shared__ int    s_last;

    // ---- helpers to form unit base addresses ----
    // unit u -> tokens i0=8u..8u+7 ; batch b=i0>>10 ; hw0=i0&1023 (multiple of 8)
    #define X_ADDR(u)  (x  + ((size_t)(((u) * 8) >> 10) * DD * HWSZ) + (((u) * 8) & (HWSZ - 1)) + (size_t)ld * HWSZ + lh)
    #define MU_ADDR(u) (mu + (size_t)((u) * 8 + t) * DD + 4 * dg)
    #define LV_ADDR(u) (lv + (size_t)((u) * 8 + t) * DD + 4 * dg)

    // ---- prologue: prefetch unit c ----
    float4 xt    = __ldg((const float4*)X_ADDR(c));
    float4 pm[2], pl[2];
    pm[0] = __ldg((const float4*)MU_ADDR(c));
    pl[0] = __ldg((const float4*)LV_ADDR(c));

    // accumulators
    float  v0=0.f,v1=0.f,v2=0.f,v3=0.f;     // iv sums (per owned d, this CTA's tokens)
    float  w0=0.f,w1=0.f,w2=0.f,w3=0.f;     // mu*iv sums
    float  sxl=0.f, sx2l=0.f;               // x stats for row ld (this thread's hw halves)
    double accP = 0.0, accR = 0.0;

    int k = 0;
    for (int u = c; u < NUNITS; u += NBLOCKS, k++) {
        const int p  = k & 1;
        const int un = u + NBLOCKS;
        const int uc = (un < NUNITS) ? un : u;      // clamped prefetch target

        __syncthreads();                 // xs[p] free (its readers ran at k-2)

        // commit x tile for unit u (xt holds unit u), accumulate x stats
        {
            sxl  += xt.x + xt.y + xt.z + xt.w;
            sx2l += xt.x*xt.x + xt.y*xt.y + xt.z*xt.z + xt.w*xt.w;
            float* bse = &xs[p][0];
            bse[(lh + 0) * SROW + ld] = xt.x;
            bse[(lh + 1) * SROW + ld] = xt.y;
            bse[(lh + 2) * SROW + ld] = xt.z;
            bse[(lh + 3) * SROW + ld] = xt.w;
        }
        // prefetch next unit (clamped; garbage never consumed on last iter)
        xt = __ldg((const float4*)X_ADDR(uc));

        const float4 cm = pm[p];
        const float4 cl = pl[p];
        pm[1 - p] = __ldg((const float4*)MU_ADDR(uc));
        pl[1 - p] = __ldg((const float4*)LV_ADDR(uc));

        __syncthreads();                 // xs[p] visible to all

        // one conflict-free LDS.128: x[token t of unit u][4dg..4dg+3]
        const float4 xv = *(const float4*)&xs[p][t * SROW + 4 * dg];

        const float i0v = __expf(-cl.x), i1v = __expf(-cl.y);
        const float i2v = __expf(-cl.z), i3v = __expf(-cl.w);

        float pc = 0.f, rc = 0.f, dx;
        dx = xv.x - cm.x; pc += dx*dx*i0v; rc += cm.x*cm.x*i0v; v0 += i0v; w0 += cm.x*i0v;
        dx = xv.y - cm.y; pc += dx*dx*i1v; rc += cm.y*cm.y*i1v; v1 += i1v; w1 += cm.y*i1v;
        dx = xv.z - cm.z; pc += dx*dx*i2v; rc += cm.z*cm.z*i2v; v2 += i2v; w2 += cm.z*i2v;
        dx = xv.w - cm.w; pc += dx*dx*i3v; rc += cm.w*cm.w*i3v; v3 += i3v; w3 += cm.w*i3v;
        accP += (double)pc;
        accR += (double)rc;
    }

    // ---- epilogue (once per CTA) ----

    // P / R: warp -> block -> global
#pragma unroll
    for (int o = 16; o > 0; o >>= 1) {
        accP += __shfl_down_sync(0xffffffffu, accP, o);
        accR += __shfl_down_sync(0xffffffffu, accR, o);
    }
    if (lane == 0) sred[warp] = accP;
    __syncthreads();
    if (warp == 0) {
        double tt = sred[lane];
#pragma unroll
        for (int o = 16; o > 0; o >>= 1) tt += __shfl_down_sync(0xffffffffu, tt, o);
        if (lane == 0) atomicAdd(&g_P, tt);
    }
    __syncthreads();
    if (lane == 0) sred[warp] = accR;
    __syncthreads();
    if (warp == 0) {
        double tt = sred[lane];
#pragma unroll
        for (int o = 16; o > 0; o >>= 1) tt += __shfl_down_sync(0xffffffffu, tt, o);
        if (lane == 0) atomicAdd(&g_R, tt);
    }

    // x stats: row ld has two halves (tid, tid^1) -> pair-combine, even lane commits
    sxl  += __shfl_xor_sync(0xffffffffu, sxl,  1);
    sx2l += __shfl_xor_sync(0xffffffffu, sx2l, 1);
    if ((tid & 1) == 0) {
        atomicAdd(&g_sx[ld],  (double)sxl);
        atomicAdd(&g_sx2[ld], (double)sx2l);
    }

    // iv / mu*iv: reduce over the 8 token rows via smem (reuse xs), then atomics
    __syncthreads();
    *(float4*)&xs[0][t * SROW + 4 * dg] = make_float4(v0, v1, v2, v3);
    *(float4*)&xs[1][t * SROW + 4 * dg] = make_float4(w0, w1, w2, w3);
    __syncthreads();
    if (tid < DD) {
        float s1 = 0.f, s2 = 0.f;
#pragma unroll
        for (int r = 0; r < 8; r++) { s1 += xs[0][r * SROW + tid]; s2 += xs[1][r * SROW + tid]; }
        atomicAdd(&g_siv[tid],   (double)s1);
        atomicAdd(&g_smuiv[tid], (double)s2);
    }

    // ---- fused finalize: last-arriving CTA combines & resets ----
    __threadfence();
    if (tid == 0) s_last = (atomicAdd(&g_done, 1) == NBLOCKS - 1) ? 1 : 0;
    __syncthreads();
    if (s_last) {
        __threadfence();
        const double invN = 1.0 / (double)NN;
        double q = 0.0;
        if (tid < DD) {
            q = (g_sx2[tid] * invN) * g_siv[tid]
              - 2.0 * (g_sx[tid] * invN) * g_smuiv[tid];
            g_sx[tid] = 0.0; g_sx2[tid] = 0.0; g_siv[tid] = 0.0; g_smuiv[tid] = 0.0;
        }
#pragma unroll
        for (int o = 16; o > 0; o >>= 1) q += __shfl_down_sync(0xffffffffu, q, o);
        if (lane == 0) sred[warp] = q;
        __syncthreads();
        if (warp == 0) {
            double tt = sred[lane];
#pragma unroll
            for (int o = 16; o > 0; o >>= 1) tt += __shfl_down_sync(0xffffffffu, tt, o);
            if (lane == 0) {
                const double Q = tt + g_R;
                out[0] = (float)(-0.5 * invN * (g_P - Q));
                g_P = 0.0; g_R = 0.0; g_done = 0;
            }
        }
    }
}

extern "C" void kernel_launch(void* const* d_in, const int* in_sizes, int n_in,
                              void* d_out, int out_size)
{
    const float* x  = (const float*)d_in[0];
    const float* mu = (const float*)d_in[1];
    const float* lv = (const float*)d_in[2];
    float* out = (float*)d_out;

    club_persist<<<NBLOCKS, 1024>>>(x, mu, lv, out);
}